// round 10
// baseline (speedup 1.0000x reference)
#include <cuda_runtime.h>
#include <cuda_bf16.h>

// CompositeLoss fused single-kernel, R8: one column-group per thread
// (16 LDG.128/thread, 11 accumulators) to fit 64 regs -> 4 CTAs/SM (50% occ),
// full unroll for ptxas load batching, log2-domain focal math.

#define PLANES   320          // B*C = 16*20
#define SUBS     8            // blocks per plane
#define THREADS  256          // 8 warps
#define F4_PLANE 16384        // HW/4
#define NTOT_D   20971520.0

// Per-plane moments: [mass, sty, stx, sp, spy, spx, spyy, spxx]
__device__ float        g_plane[PLANES * 8];
// Global sums: [fl(log2-scale), sum (x-t)^2, sum |x|]
__device__ double       g_glob[3];
__device__ unsigned int g_count;

__device__ __forceinline__ float frcp(float x) {
    float r; asm("rcp.approx.f32 %0, %1;" : "=f"(r) : "f"(x)); return r;
}
__device__ __forceinline__ float fex2(float x) {
    float r; asm("ex2.approx.f32 %0, %1;" : "=f"(r) : "f"(x)); return r;
}
__device__ __forceinline__ float flg2(float x) {
    float r; asm("lg2.approx.f32 %0, %1;" : "=f"(r) : "f"(x)); return r;
}

// One float4 (4 elements): focal/sparsity terms + group moments.
__device__ __forceinline__ void grp4(const float4 pv, const float4 tv,
                                     float& fl, float& sq, float& ab,
                                     float& psum, float& q1, float& q2,
                                     float& tsum, float& tq1)
{
    const float xv[4] = {pv.x, pv.y, pv.z, pv.w};
    const float tt[4] = {tv.x, tv.y, tv.z, tv.w};
    float p[4];
    #pragma unroll
    for (int j = 0; j < 4; j++) {
        const float x = xv[j];
        const float t = tt[j];                      // 0.0f or 1.0f
        const float m = x * -1.4426950408889634f;   // -x*log2(e)
        const float e = fex2(m);                    // e^{-x}
        const float s = e + 1.0f;
        const float r = frcp(s);                    // p = sigmoid(x)
        const float L = flg2(s);                    // -lg2(p)
        const float d2 = m - L;                     // lg2(1-p)
        const float lg = fmaf(t, -m, d2);           // lg2(pt)
        const float k = fmaf(r, -2.0f, 1.0f);
        const float u = fmaf(t, k, r);              // 1 - pt
        const float a = fmaf(t, -0.5f, 0.75f);      // alpha_t
        fl = fmaf(a * (u * u), lg, fl);             // (negative), *ln2 at end
        const float dd = x - t;
        sq = fmaf(dd, dd, sq);
        ab += fabsf(x);
        p[j] = r;
    }
    psum += (p[0] + p[1]) + (p[2] + p[3]);
    q1   += fmaf(3.0f, p[3], fmaf(2.0f, p[2], p[1]));
    q2   += fmaf(9.0f, p[3], fmaf(4.0f, p[2], p[1]));
    tsum += (tt[0] + tt[1]) + (tt[2] + tt[3]);
    tq1  += fmaf(3.0f, tt[3], fmaf(2.0f, tt[2], tt[1]));
}

__global__ __launch_bounds__(THREADS, 4) void composite_kernel(
    const float4* __restrict__ pred, const float4* __restrict__ tgt,
    float* __restrict__ out, int out_size)
{
    const int plane = blockIdx.x >> 3;
    const int sub   = blockIdx.x & 7;
    const int half  = sub & 1;          // column half: 0 -> cols [0,128), 1 -> [128,256)
    const int rb    = sub >> 1;         // row block: 64 rows each
    const int warp  = threadIdx.x >> 5;
    const int lane  = threadIdx.x & 31;

    const int   row0 = rb * 64 + warp * 8;              // 8 rows per warp
    const float x0   = (float)(half * 128 + lane * 4);  // base column of this thread

    const int base = plane * F4_PLANE + row0 * 64 + half * 32 + lane;
    const float4* __restrict__ pp = pred + base;
    const float4* __restrict__ tp = tgt  + base;

    float fl = 0.f, sq = 0.f, ab = 0.f;
    float P = 0.f, Q1 = 0.f, Q2 = 0.f;
    float spy = 0.f, spyy = 0.f;
    float T = 0.f, TQ1 = 0.f, sty = 0.f;

    #pragma unroll
    for (int r = 0; r < 8; r++) {
        const float4 pv = pp[r * 64];
        const float4 tv = tp[r * 64];
        float ps = 0.f, q1 = 0.f, q2 = 0.f, ts = 0.f, tq = 0.f;
        grp4(pv, tv, fl, sq, ab, ps, q1, q2, ts, tq);
        P += ps; Q1 += q1; Q2 += q2;
        T += ts; TQ1 += tq;
        const float y = (float)(row0 + r);
        spy  = fmaf(ps, y, spy);
        spyy = fmaf(ps, y * y, spyy);
        sty  = fmaf(ts, y, sty);
    }

    // Per-thread x folds: x = x0 + j
    const float sp   = P;
    const float spx  = fmaf(x0, P, Q1);
    const float spxx = fmaf(x0 * x0, P, fmaf(2.0f * x0, Q1, Q2));
    const float mass = T;
    const float stx  = fmaf(x0, T, TQ1);

    // ---- block reduction of 11 values ----
    float vals[11] = {fl, sq, ab, mass, sty, stx, sp, spy, spx, spyy, spxx};
    #pragma unroll
    for (int offm = 16; offm > 0; offm >>= 1) {
        #pragma unroll
        for (int k = 0; k < 11; k++)
            vals[k] += __shfl_down_sync(0xffffffffu, vals[k], offm);
    }
    __shared__ float smem[THREADS / 32][11];
    if (lane == 0) {
        #pragma unroll
        for (int k = 0; k < 11; k++) smem[warp][k] = vals[k];
    }
    __syncthreads();

    __shared__ bool s_last;
    if (threadIdx.x == 0) {
        float rr[11];
        #pragma unroll
        for (int k = 0; k < 11; k++) rr[k] = smem[0][k];
        for (int w = 1; w < THREADS / 32; w++)
            #pragma unroll
            for (int k = 0; k < 11; k++) rr[k] += smem[w][k];

        atomicAdd(&g_glob[0], (double)rr[0]);
        atomicAdd(&g_glob[1], (double)rr[1]);
        atomicAdd(&g_glob[2], (double)rr[2]);
        float* Pp = &g_plane[plane * 8];
        #pragma unroll
        for (int k = 0; k < 8; k++) atomicAdd(&Pp[k], rr[3 + k]);

        __threadfence();
        const unsigned cc = atomicAdd(&g_count, 1u);
        s_last = (cc == gridDim.x - 1);
    }
    __syncthreads();
    if (!s_last) return;

    // ---- last block: finalize + reset ----
    __threadfence();
    __shared__ float s_conc;
    __shared__ int   s_nv;
    if (threadIdx.x == 0) { s_conc = 0.f; s_nv = 0; }
    __syncthreads();

    for (int i = threadIdx.x; i < PLANES; i += THREADS) {
        const float* Pp = &g_plane[i * 8];
        const float m = Pp[0];
        if (m > 0.0f) {
            const float cy = Pp[1] / m;
            const float cx = Pp[2] / m;
            const float num = Pp[6] - 2.0f * cy * Pp[4] + cy * cy * Pp[3]
                            + Pp[7] - 2.0f * cx * Pp[5] + cx * cx * Pp[3];
            atomicAdd(&s_conc, num * (1.0f / 65536.0f));
            atomicAdd(&s_nv, 1);
        }
    }
    __syncthreads();

    if (threadIdx.x == 0) {
        const double N = NTOT_D;
        const float focal    = (float)(-0.6931471805599453 * g_glob[0] / N);
        const float sparsity = (float)((g_glob[1] + g_glob[2]) / N);
        const float conc     = (s_nv > 0) ? (s_conc / (float)s_nv) : 0.0f;
        out[0] = focal + 0.8f * sparsity + 1.5f * conc;
        if (out_size >= 4) { out[1] = focal; out[2] = sparsity; out[3] = conc; }
    }
    __syncthreads();

    // reset accumulators for next launch (graph replay)
    for (int i = threadIdx.x; i < PLANES * 8; i += THREADS) g_plane[i] = 0.0f;
    if (threadIdx.x < 3) g_glob[threadIdx.x] = 0.0;
    if (threadIdx.x == 0) g_count = 0u;
}

extern "C" void kernel_launch(void* const* d_in, const int* in_sizes, int n_in,
                              void* d_out, int out_size) {
    const float4* pred = (const float4*)d_in[0];
    const float4* tgt  = (const float4*)d_in[1];
    composite_kernel<<<PLANES * SUBS, THREADS>>>(pred, tgt, (float*)d_out, out_size);
}